// round 11
// baseline (speedup 1.0000x reference)
#include <cuda_runtime.h>
#include <cuda_bf16.h>
#include <cuda_fp16.h>
#include <cstdint>
#include <cstddef>

// ---------------------------------------------------------------------------
// MultiHeadSelfAttention B=2,S=2048,Dm=1024,H=16,Dk=64
// Everything single-pass fp16 HMMA with fp32 accumulators.
// Flash: unnormalized exp softmax, nb-major S chunks (low reg pressure),
// 3 CTAs/SM target. GEMM: BK=64 double-buffered cp.async.
// ---------------------------------------------------------------------------
#define Bb   2
#define Ss   2048
#define Dm   1024
#define Hh   16
#define Dk   64
#define MR   4096

#define QSCALE 0.18033688011112042f   // log2(e)/8

// ---------------- scratch ---------------------------------------------------
__device__ __half g_xs[(size_t)MR * Dm];
__device__ __half g_Qs[(size_t)MR * Dm];
__device__ __half g_Ks[(size_t)MR * Dm];
__device__ __half g_Vs[(size_t)MR * Dm];
__device__ __half g_As[(size_t)MR * Dm];
__device__ __half g_wT[4][(size_t)Dm * Dm];

// ---------------- helpers ---------------------------------------------------
__device__ __forceinline__ uint32_t smem_u32(const void* p) {
    uint32_t a;
    asm("{ .reg .u64 t; cvta.to.shared.u64 t, %1; cvt.u32.u64 %0, t; }"
        : "=r"(a) : "l"(p));
    return a;
}
__device__ __forceinline__ void cp_async16(uint32_t s, const void* g) {
    asm volatile("cp.async.cg.shared.global [%0], [%1], 16;" :: "r"(s), "l"(g));
}
#define CP_COMMIT() asm volatile("cp.async.commit_group;" ::: "memory")
#define CP_WAIT0()  asm volatile("cp.async.wait_group 0;" ::: "memory")

__device__ __forceinline__ float ex2(float x) {
    float r;
    asm("ex2.approx.f32 %0, %1;" : "=f"(r) : "f"(x));
    return r;
}
__device__ __forceinline__ void mma_f16(float* d, const uint32_t* a, const uint32_t* b) {
    asm volatile(
        "mma.sync.aligned.m16n8k16.row.col.f32.f16.f16.f32 "
        "{%0,%1,%2,%3}, {%4,%5,%6,%7}, {%8,%9}, {%0,%1,%2,%3};\n"
        : "+f"(d[0]), "+f"(d[1]), "+f"(d[2]), "+f"(d[3])
        : "r"(a[0]), "r"(a[1]), "r"(a[2]), "r"(a[3]), "r"(b[0]), "r"(b[1]));
}
__device__ __forceinline__ void ldsm_x4(uint32_t* r, uint32_t addr) {
    asm volatile("ldmatrix.sync.aligned.m8n8.x4.shared.b16 {%0,%1,%2,%3}, [%4];"
                 : "=r"(r[0]), "=r"(r[1]), "=r"(r[2]), "=r"(r[3]) : "r"(addr));
}
__device__ __forceinline__ void ldsm_x4_t(uint32_t* r, uint32_t addr) {
    asm volatile("ldmatrix.sync.aligned.m8n8.x4.trans.shared.b16 {%0,%1,%2,%3}, [%4];"
                 : "=r"(r[0]), "=r"(r[1]), "=r"(r[2]), "=r"(r[3]) : "r"(addr));
}
__device__ __forceinline__ uint32_t ldsm_addr_rc(uint32_t base, int r0, int c0,
                                                 int stride, int lane) {
    int sub = lane >> 3;
    int r = r0 + ((sub & 1) << 3) + (lane & 7);
    int c = c0 + ((sub >> 1) << 3);
    return base + (uint32_t)(r * stride + c) * 2u;
}
__device__ __forceinline__ uint32_t ldsm_addr_b(uint32_t base, int n0, int k0,
                                                int stride, int lane) {
    int sub = lane >> 3;
    int n = n0 + ((sub >> 1) << 3) + (lane & 7);
    int k = k0 + ((sub & 1) << 3);
    return base + (uint32_t)(n * stride + k) * 2u;
}
__device__ __forceinline__ uint32_t pack_h2(float lo, float hi) {
    __half2 t = __floats2half2_rn(lo, hi);
    return *reinterpret_cast<uint32_t*>(&t);
}

// ---------------- fused prep: weights transpose+cvt (z<4), x cvt (z==4) ----
__global__ __launch_bounds__(256) void prep_kernel(
    const float* __restrict__ x,
    const float* __restrict__ w0, const float* __restrict__ w1,
    const float* __restrict__ w2, const float* __restrict__ w3,
    __half* __restrict__ xs, __half* __restrict__ wTB)
{
    int z = blockIdx.z;
    int tx = threadIdx.x, ty = threadIdx.y;  // block (32,8)
    if (z == 4) {
        // convert x: 4M floats; 1024 blocks x 256 thr x 4 float4
        int bid = blockIdx.y * 32 + blockIdx.x;
        int t0 = (bid * 256 + ty * 32 + tx) * 4;
        const float4* in = (const float4*)x;
        __half2* out = (__half2*)xs;
        #pragma unroll
        for (int j = 0; j < 4; j++) {
            float4 v = in[t0 + j];
            out[2 * (t0 + j)]     = __floats2half2_rn(v.x, v.y);
            out[2 * (t0 + j) + 1] = __floats2half2_rn(v.z, v.w);
        }
        return;
    }
    __shared__ float t[32][33];
    const float* w = (z == 0) ? w0 : (z == 1) ? w1 : (z == 2) ? w2 : w3;
    __half* wT = wTB + (size_t)z * Dm * Dm;
    int n0 = blockIdx.x * 32, k0 = blockIdx.y * 32;
    #pragma unroll
    for (int j = 0; j < 4; j++)
        t[ty + 8 * j][tx] = w[(size_t)(k0 + ty + 8 * j) * Dm + n0 + tx];
    __syncthreads();
    #pragma unroll
    for (int j = 0; j < 4; j++)
        wT[(size_t)(n0 + ty + 8 * j) * Dm + k0 + tx] = __float2half(t[tx][ty + 8 * j]);
}

// ---------------------------------------------------------------------------
// Single-pass fp16 HMMA GEMM: C[M,N] = A[M,K] @ BT[N,K]^T (+bias) (*scale)
// 128x128x64 tiles, 8 warps (2m x 4n), cp.async double-buffered, z-fused.
// OUT: 0 = fp32 + bias, 2 = fp16 (bias then scale).
// ---------------------------------------------------------------------------
#define GST 72
#define GT_TILE (128 * GST)               // halves per matrix tile (9216)
#define GT_BUF  (2 * GT_TILE)             // A + B
#define GEMM_SMEM_BYTES (2 * GT_BUF * 2)  // 73728

struct GemmJob {
    const __half* B;
    const float* bias;
    float* Cf;
    __half* Cs;
    float scale;
};
struct GemmJobs3 { GemmJob j[3]; };

template<int OUT>
__global__ __launch_bounds__(256) void tc_gemm(
    const __half* __restrict__ A, GemmJobs3 jobs)
{
    extern __shared__ __align__(16) __half sm[];
    const GemmJob job = jobs.j[blockIdx.z];

    const int tid = threadIdx.x;
    const int warp = tid >> 5, lane = tid & 31;
    const int wm = (warp >> 2) * 64;
    const int wn = (warp & 3) * 32;
    const int m0 = blockIdx.y * 128, n0 = blockIdx.x * 128;
    const uint32_t smb = smem_u32(sm);

    float acc[4][4][4];
    #pragma unroll
    for (int mi = 0; mi < 4; mi++)
        #pragma unroll
        for (int nf = 0; nf < 4; nf++)
            #pragma unroll
            for (int j = 0; j < 4; j++) acc[mi][nf][j] = 0.0f;

    // per-tile: 128 rows x 8 chunks(16B) = 1024 chunks; 4 per thread
    auto issue_loads = [&](int kc, int buf) {
        uint32_t base = smb + (uint32_t)buf * GT_BUF * 2;
        const __half* srcs[2] = { A, job.B };
        #pragma unroll
        for (int t2 = 0; t2 < 2; t2++) {
            int row = (t2 == 0) ? m0 : n0;
            const __half* src = srcs[t2];
            #pragma unroll
            for (int t = 0; t < 4; t++) {
                int c = tid + t * 256;         // 0..1023
                int r = c >> 3, ch = c & 7;
                size_t g = (size_t)(row + r) * Dm + kc * 64 + ch * 8;
                uint32_t s = base + (uint32_t)(t2 * GT_TILE + r * GST + ch * 8) * 2;
                cp_async16(s, src + g);
            }
        }
    };

    issue_loads(0, 0);
    CP_COMMIT();
    CP_WAIT0();
    __syncthreads();

    int buf = 0;
    const int NK = Dm / 64;
    for (int kc = 0; kc < NK; kc++) {
        if (kc + 1 < NK) { issue_loads(kc + 1, buf ^ 1); CP_COMMIT(); }

        uint32_t bA = smb + (uint32_t)buf * GT_BUF * 2;
        uint32_t sA_u = bA;
        uint32_t sB_u = bA + GT_TILE * 2;

        #pragma unroll
        for (int k16 = 0; k16 < 4; k16++) {
            uint32_t bh[2][4];
            #pragma unroll
            for (int nb = 0; nb < 2; nb++)
                ldsm_x4(bh[nb], ldsm_addr_b(sB_u, wn + nb * 16, k16 * 16, GST, lane));
            #pragma unroll
            for (int mi = 0; mi < 4; mi++) {
                uint32_t ah[4];
                ldsm_x4(ah, ldsm_addr_rc(sA_u, wm + mi * 16, k16 * 16, GST, lane));
                #pragma unroll
                for (int nf = 0; nf < 4; nf++)
                    mma_f16(acc[mi][nf], ah, &bh[nf >> 1][(nf & 1) * 2]);
            }
        }
        if (kc + 1 < NK) CP_WAIT0();
        __syncthreads();
        buf ^= 1;
    }

    #pragma unroll
    for (int mi = 0; mi < 4; mi++) {
        int row = m0 + wm + mi * 16 + (lane >> 2);
        #pragma unroll
        for (int nf = 0; nf < 4; nf++) {
            int col = n0 + wn + nf * 8 + (lane & 3) * 2;
            float b0 = job.bias[col], b1 = job.bias[col + 1];
            #pragma unroll
            for (int half = 0; half < 2; half++) {
                int r = row + half * 8;
                float v0 = acc[mi][nf][half * 2 + 0] + b0;
                float v1 = acc[mi][nf][half * 2 + 1] + b1;
                size_t o = (size_t)r * Dm + col;
                if (OUT == 2) {
                    v0 *= job.scale;
                    v1 *= job.scale;
                    *(__half2*)(job.Cs + o) = __floats2half2_rn(v0, v1);
                } else {
                    float2 v; v.x = v0; v.y = v1;
                    *(float2*)(job.Cf + o) = v;
                }
            }
        }
    }
}

// ---------------------------------------------------------------------------
// Flash attention, single-pass fp16 HMMA. 4 warps x 32 q-rows (Br=128),
// Bc=64, Dk=64. Q frags register-resident; K/V cp.async double-buffered.
// nb-major S chunks: live S accumulator is 16 regs -> 3 CTAs/SM target.
// p = 2^(q.k) (Q pre-scaled); output fp16.
// ---------------------------------------------------------------------------
#define FST 72
#define FQ_B   (128 * FST * 2)                 // 18432
#define FT_B   (64 * FST * 2)                  // 9216
#define FBUF_B (2 * FT_B)
#define FLASH_SMEM_BYTES (FQ_B + 2 * FBUF_B)   // 55296

__global__ __launch_bounds__(128, 3) void flash_f16(
    const __half* __restrict__ Qs, const __half* __restrict__ Ks,
    const __half* __restrict__ Vs, __half* __restrict__ As)
{
    extern __shared__ __align__(16) __half fsm[];
    const int tid = threadIdx.x;
    const int warp = tid >> 5, lane = tid & 31;
    const int qt = blockIdx.x, h = blockIdx.y, b = blockIdx.z;
    const int wq = warp * 32;
    const uint32_t smb = smem_u32(fsm);

    // ---- stage Q (128x64 fp16) ----
    #pragma unroll
    for (int t = 0; t < 8; t++) {
        int c = tid + t * 128;
        int r = c >> 3, ch = c & 7;
        size_t g = (size_t)(b * Ss + qt * 128 + r) * Dm + h * Dk + ch * 8;
        *(uint4*)(&fsm[r * FST + ch * 8]) = *(const uint4*)(Qs + g);
    }

    auto issue_kv = [&](int kt, int buf) {
        uint32_t base = smb + FQ_B + (uint32_t)buf * FBUF_B;
        const __half* srcs[2] = { Ks, Vs };
        #pragma unroll
        for (int t = 0; t < 8; t++) {
            int c = tid + t * 128;
            int tile = c >> 9, idx = c & 511;
            int r = idx >> 3, ch = idx & 7;
            size_t g = (size_t)(b * Ss + kt * 64 + r) * Dm + h * Dk + ch * 8;
            uint32_t s = base + (uint32_t)tile * FT_B + (uint32_t)(r * FST + ch * 8) * 2;
            cp_async16(s, srcs[tile] + g);
        }
    };

    issue_kv(0, 0);
    CP_COMMIT();
    CP_WAIT0();
    __syncthreads();

    // ---- Q fragments resident in registers ----
    uint32_t qf[2][4][4];
    #pragma unroll
    for (int mi = 0; mi < 2; mi++)
        #pragma unroll
        for (int ki = 0; ki < 4; ki++)
            ldsm_x4(qf[mi][ki], ldsm_addr_rc(smb, wq + mi * 16, ki * 16, FST, lane));

    float oacc[2][8][4];
    #pragma unroll
    for (int mi = 0; mi < 2; mi++)
        #pragma unroll
        for (int nf = 0; nf < 8; nf++)
            #pragma unroll
            for (int j = 0; j < 4; j++) oacc[mi][nf][j] = 0.0f;
    float lsum[2][2] = {{0.0f, 0.0f}, {0.0f, 0.0f}};

    int buf = 0;
    const int NT = Ss / 64;
    for (int kt = 0; kt < NT; kt++) {
        if (kt + 1 < NT) { issue_kv(kt + 1, buf ^ 1); CP_COMMIT(); }

        uint32_t sKs = smb + FQ_B + (uint32_t)buf * FBUF_B;
        uint32_t sVs = sKs + FT_B;

        // ---- S + exp + P-frag per 16-col chunk (nb-major, low reg) ----
        uint32_t aP[2][4][4];
        #pragma unroll
        for (int nb = 0; nb < 4; nb++) {
            float sl[2][2][4];
            #pragma unroll
            for (int mi = 0; mi < 2; mi++)
                #pragma unroll
                for (int hf = 0; hf < 2; hf++)
                    #pragma unroll
                    for (int j = 0; j < 4; j++) sl[mi][hf][j] = 0.0f;

            #pragma unroll
            for (int ki = 0; ki < 4; ki++) {
                uint32_t kf[4];
                ldsm_x4(kf, ldsm_addr_b(sKs, nb * 16, ki * 16, FST, lane));
                #pragma unroll
                for (int hf = 0; hf < 2; hf++) {
                    mma_f16(sl[0][hf], qf[0][ki], &kf[hf * 2]);
                    mma_f16(sl[1][hf], qf[1][ki], &kf[hf * 2]);
                }
            }
            #pragma unroll
            for (int mi = 0; mi < 2; mi++) {
                #pragma unroll
                for (int hf = 0; hf < 2; hf++) {
                    sl[mi][hf][0] = ex2(sl[mi][hf][0]);
                    sl[mi][hf][1] = ex2(sl[mi][hf][1]);
                    sl[mi][hf][2] = ex2(sl[mi][hf][2]);
                    sl[mi][hf][3] = ex2(sl[mi][hf][3]);
                    lsum[mi][0] += sl[mi][hf][0] + sl[mi][hf][1];
                    lsum[mi][1] += sl[mi][hf][2] + sl[mi][hf][3];
                }
                aP[mi][nb][0] = pack_h2(sl[mi][0][0], sl[mi][0][1]);
                aP[mi][nb][1] = pack_h2(sl[mi][0][2], sl[mi][0][3]);
                aP[mi][nb][2] = pack_h2(sl[mi][1][0], sl[mi][1][1]);
                aP[mi][nb][3] = pack_h2(sl[mi][1][2], sl[mi][1][3]);
            }
        }

        // ---- O += P V ----
        #pragma unroll
        for (int ki = 0; ki < 4; ki++) {
            #pragma unroll
            for (int nb = 0; nb < 4; nb++) {
                uint32_t vf[4];
                ldsm_x4_t(vf, ldsm_addr_rc(sVs, ki * 16, nb * 16, FST, lane));
                #pragma unroll
                for (int half = 0; half < 2; half++) {
                    mma_f16(oacc[0][nb * 2 + half], aP[0][ki], &vf[half * 2]);
                    mma_f16(oacc[1][nb * 2 + half], aP[1][ki], &vf[half * 2]);
                }
            }
        }
        if (kt + 1 < NT) CP_WAIT0();
        __syncthreads();
        buf ^= 1;
    }

    #pragma unroll
    for (int mi = 0; mi < 2; mi++)
        #pragma unroll
        for (int hf = 0; hf < 2; hf++) {
            #pragma unroll
            for (int off = 1; off < 4; off <<= 1)
                lsum[mi][hf] += __shfl_xor_sync(0xffffffffu, lsum[mi][hf], off);
        }

    #pragma unroll
    for (int mi = 0; mi < 2; mi++) {
        float inv0 = 1.0f / lsum[mi][0], inv1 = 1.0f / lsum[mi][1];
        int row = b * Ss + qt * 128 + wq + mi * 16 + (lane >> 2);
        #pragma unroll
        for (int nf = 0; nf < 8; nf++) {
            int col = h * Dk + nf * 8 + (lane & 3) * 2;
            #pragma unroll
            for (int half = 0; half < 2; half++) {
                float inv = half ? inv1 : inv0;
                float v0 = oacc[mi][nf][half * 2 + 0] * inv;
                float v1 = oacc[mi][nf][half * 2 + 1] * inv;
                size_t o = (size_t)(row + half * 8) * Dm + col;
                *(__half2*)(As + o) = __floats2half2_rn(v0, v1);
            }
        }
    }
}

// ---------------------------------------------------------------------------
extern "C" void kernel_launch(void* const* d_in, const int* in_sizes, int n_in,
                              void* d_out, int out_size)
{
    const float* x   = (const float*)d_in[0];
    const float* w_q = (const float*)d_in[1];
    const float* b_q = (const float*)d_in[2];
    const float* w_k = (const float*)d_in[3];
    const float* b_k = (const float*)d_in[4];
    const float* w_v = (const float*)d_in[5];
    const float* b_v = (const float*)d_in[6];
    const float* w_o = (const float*)d_in[7];
    const float* b_o = (const float*)d_in[8];
    float* out = (float*)d_out;

    __half *xs, *Qsp, *Ksp, *Vsp, *Asp, *wT;
    cudaGetSymbolAddress((void**)&xs, g_xs);
    cudaGetSymbolAddress((void**)&Qsp, g_Qs);
    cudaGetSymbolAddress((void**)&Ksp, g_Ks);
    cudaGetSymbolAddress((void**)&Vsp, g_Vs);
    cudaGetSymbolAddress((void**)&Asp, g_As);
    cudaGetSymbolAddress((void**)&wT, g_wT);
    const size_t WSZ = (size_t)Dm * Dm;

    cudaFuncSetAttribute(tc_gemm<0>,
                         cudaFuncAttributeMaxDynamicSharedMemorySize, GEMM_SMEM_BYTES);
    cudaFuncSetAttribute(tc_gemm<2>,
                         cudaFuncAttributeMaxDynamicSharedMemorySize, GEMM_SMEM_BYTES);
    cudaFuncSetAttribute(flash_f16,
                         cudaFuncAttributeMaxDynamicSharedMemorySize, FLASH_SMEM_BYTES);

    // fused prep: transpose+convert 4 weights (z<4) + convert x (z==4)
    {
        dim3 tg(32, 32, 5), tb(32, 8);
        prep_kernel<<<tg, tb>>>(x, w_q, w_k, w_v, w_o, xs, wT);
    }

    // fused QKV projection -> fp16 (Q pre-scaled by log2e/8)
    {
        GemmJobs3 jobs;
        jobs.j[0] = { wT + 0 * WSZ, b_q, nullptr, Qsp, QSCALE };
        jobs.j[1] = { wT + 1 * WSZ, b_k, nullptr, Ksp, 1.0f };
        jobs.j[2] = { wT + 2 * WSZ, b_v, nullptr, Vsp, 1.0f };
        dim3 g(Dm / 128, MR / 128, 3);
        tc_gemm<2><<<g, 256, GEMM_SMEM_BYTES>>>(xs, jobs);
    }

    // flash attention (fp16 single-pass)
    {
        dim3 agrid(Ss / 128, Hh, Bb);   // (16,16,2)
        flash_f16<<<agrid, 128, FLASH_SMEM_BYTES>>>(Qsp, Ksp, Vsp, Asp);
    }

    // output projection (fp16 single-pass, fp32 out + bias)
    {
        GemmJobs3 jobs;
        jobs.j[0] = { wT + 3 * WSZ, b_o, out, nullptr, 1.0f };
        jobs.j[1] = jobs.j[0];
        jobs.j[2] = jobs.j[0];
        dim3 g(Dm / 128, MR / 128, 1);
        tc_gemm<0><<<g, 256, GEMM_SMEM_BYTES>>>(Asp, jobs);
    }
}

// round 16
// speedup vs baseline: 1.0102x; 1.0102x over previous
#include <cuda_runtime.h>
#include <cuda_bf16.h>
#include <cuda_fp16.h>
#include <cstdint>
#include <cstddef>

// ---------------------------------------------------------------------------
// MultiHeadSelfAttention B=2,S=2048,Dm=1024,H=16,Dk=64
// Everything single-pass fp16 HMMA with fp32 accumulators.
// 3-stage cp.async pipelines (wait_group 1; wait_group 0 on drain).
// Flash: unnormalized exp softmax (Q pre-scaled by log2e/8).
// ---------------------------------------------------------------------------
#define Bb   2
#define Ss   2048
#define Dm   1024
#define Hh   16
#define Dk   64
#define MR   4096

#define QSCALE 0.18033688011112042f   // log2(e)/8

// ---------------- scratch ---------------------------------------------------
__device__ __half g_xs[(size_t)MR * Dm];
__device__ __half g_Qs[(size_t)MR * Dm];
__device__ __half g_Ks[(size_t)MR * Dm];
__device__ __half g_Vs[(size_t)MR * Dm];
__device__ __half g_As[(size_t)MR * Dm];
__device__ __half g_wT[4][(size_t)Dm * Dm];

// ---------------- helpers ---------------------------------------------------
__device__ __forceinline__ uint32_t smem_u32(const void* p) {
    uint32_t a;
    asm("{ .reg .u64 t; cvta.to.shared.u64 t, %1; cvt.u32.u64 %0, t; }"
        : "=r"(a) : "l"(p));
    return a;
}
__device__ __forceinline__ void cp_async16(uint32_t s, const void* g) {
    asm volatile("cp.async.cg.shared.global [%0], [%1], 16;" :: "r"(s), "l"(g));
}
#define CP_COMMIT() asm volatile("cp.async.commit_group;" ::: "memory")
#define CP_WAIT0()  asm volatile("cp.async.wait_group 0;" ::: "memory")
#define CP_WAIT1()  asm volatile("cp.async.wait_group 1;" ::: "memory")

__device__ __forceinline__ float ex2(float x) {
    float r;
    asm("ex2.approx.f32 %0, %1;" : "=f"(r) : "f"(x));
    return r;
}
__device__ __forceinline__ void mma_f16(float* d, const uint32_t* a, const uint32_t* b) {
    asm volatile(
        "mma.sync.aligned.m16n8k16.row.col.f32.f16.f16.f32 "
        "{%0,%1,%2,%3}, {%4,%5,%6,%7}, {%8,%9}, {%0,%1,%2,%3};\n"
        : "+f"(d[0]), "+f"(d[1]), "+f"(d[2]), "+f"(d[3])
        : "r"(a[0]), "r"(a[1]), "r"(a[2]), "r"(a[3]), "r"(b[0]), "r"(b[1]));
}
__device__ __forceinline__ void ldsm_x4(uint32_t* r, uint32_t addr) {
    asm volatile("ldmatrix.sync.aligned.m8n8.x4.shared.b16 {%0,%1,%2,%3}, [%4];"
                 : "=r"(r[0]), "=r"(r[1]), "=r"(r[2]), "=r"(r[3]) : "r"(addr));
}
__device__ __forceinline__ void ldsm_x4_t(uint32_t* r, uint32_t addr) {
    asm volatile("ldmatrix.sync.aligned.m8n8.x4.trans.shared.b16 {%0,%1,%2,%3}, [%4];"
                 : "=r"(r[0]), "=r"(r[1]), "=r"(r[2]), "=r"(r[3]) : "r"(addr));
}
__device__ __forceinline__ uint32_t ldsm_addr_rc(uint32_t base, int r0, int c0,
                                                 int stride, int lane) {
    int sub = lane >> 3;
    int r = r0 + ((sub & 1) << 3) + (lane & 7);
    int c = c0 + ((sub >> 1) << 3);
    return base + (uint32_t)(r * stride + c) * 2u;
}
__device__ __forceinline__ uint32_t ldsm_addr_b(uint32_t base, int n0, int k0,
                                                int stride, int lane) {
    int sub = lane >> 3;
    int n = n0 + ((sub >> 1) << 3) + (lane & 7);
    int k = k0 + ((sub & 1) << 3);
    return base + (uint32_t)(n * stride + k) * 2u;
}
__device__ __forceinline__ uint32_t pack_h2(float lo, float hi) {
    __half2 t = __floats2half2_rn(lo, hi);
    return *reinterpret_cast<uint32_t*>(&t);
}

// ---------------- fused prep: weights transpose+cvt (z<4), x cvt (z==4) ----
__global__ __launch_bounds__(256) void prep_kernel(
    const float* __restrict__ x,
    const float* __restrict__ w0, const float* __restrict__ w1,
    const float* __restrict__ w2, const float* __restrict__ w3,
    __half* __restrict__ xs, __half* __restrict__ wTB)
{
    int z = blockIdx.z;
    int tx = threadIdx.x, ty = threadIdx.y;  // block (32,8)
    if (z == 4) {
        int bid = blockIdx.y * 32 + blockIdx.x;
        int t0 = (bid * 256 + ty * 32 + tx) * 4;
        const float4* in = (const float4*)x;
        __half2* out = (__half2*)xs;
        #pragma unroll
        for (int j = 0; j < 4; j++) {
            float4 v = in[t0 + j];
            out[2 * (t0 + j)]     = __floats2half2_rn(v.x, v.y);
            out[2 * (t0 + j) + 1] = __floats2half2_rn(v.z, v.w);
        }
        return;
    }
    __shared__ float t[32][33];
    const float* w = (z == 0) ? w0 : (z == 1) ? w1 : (z == 2) ? w2 : w3;
    __half* wT = wTB + (size_t)z * Dm * Dm;
    int n0 = blockIdx.x * 32, k0 = blockIdx.y * 32;
    #pragma unroll
    for (int j = 0; j < 4; j++)
        t[ty + 8 * j][tx] = w[(size_t)(k0 + ty + 8 * j) * Dm + n0 + tx];
    __syncthreads();
    #pragma unroll
    for (int j = 0; j < 4; j++)
        wT[(size_t)(n0 + ty + 8 * j) * Dm + k0 + tx] = __float2half(t[tx][ty + 8 * j]);
}

// ---------------------------------------------------------------------------
// Single-pass fp16 HMMA GEMM: C[M,N] = A[M,K] @ BT[N,K]^T (+bias) (*scale)
// 128x128x32 tiles, 8 warps (2m x 4n), 3-stage cp.async pipeline, z-fused.
// OUT: 0 = fp32 + bias, 2 = fp16 (bias then scale).
// ---------------------------------------------------------------------------
#define GST 40
#define GT_TILE (128 * GST)               // halves per matrix tile
#define GT_BUF  (2 * GT_TILE)             // A + B
#define G_STAGES 3
#define GEMM_SMEM_BYTES (G_STAGES * GT_BUF * 2)  // 61440

struct GemmJob {
    const __half* B;
    const float* bias;
    float* Cf;
    __half* Cs;
    float scale;
};
struct GemmJobs3 { GemmJob j[3]; };

template<int OUT>
__global__ __launch_bounds__(256) void tc_gemm(
    const __half* __restrict__ A, GemmJobs3 jobs)
{
    extern __shared__ __align__(16) __half sm[];
    const GemmJob job = jobs.j[blockIdx.z];

    const int tid = threadIdx.x;
    const int warp = tid >> 5, lane = tid & 31;
    const int wm = (warp >> 2) * 64;
    const int wn = (warp & 3) * 32;
    const int m0 = blockIdx.y * 128, n0 = blockIdx.x * 128;
    const uint32_t smb = smem_u32(sm);

    const int lr0 = tid >> 2, lch0 = tid & 3;        // rows 0..63
    const int c1 = tid + 256;
    const int lr1 = c1 >> 2, lch1 = c1 & 3;          // rows 64..127

    float acc[4][4][4];
    #pragma unroll
    for (int mi = 0; mi < 4; mi++)
        #pragma unroll
        for (int nf = 0; nf < 4; nf++)
            #pragma unroll
            for (int j = 0; j < 4; j++) acc[mi][nf][j] = 0.0f;

    auto issue_loads = [&](int kc, int buf) {
        uint32_t base = smb + (uint32_t)buf * GT_BUF * 2;
        const __half* srcs[2] = { A, job.B };
        #pragma unroll
        for (int t2 = 0; t2 < 2; t2++) {
            int row = (t2 == 0) ? m0 : n0;
            const __half* src = srcs[t2];
            size_t g0 = (size_t)(row + lr0) * Dm + kc * 32 + lch0 * 8;
            size_t g1 = (size_t)(row + lr1) * Dm + kc * 32 + lch1 * 8;
            uint32_t s0 = base + (uint32_t)(t2 * GT_TILE + lr0 * GST + lch0 * 8) * 2;
            uint32_t s1 = base + (uint32_t)(t2 * GT_TILE + lr1 * GST + lch1 * 8) * 2;
            cp_async16(s0, src + g0);
            cp_async16(s1, src + g1);
        }
    };

    issue_loads(0, 0);
    CP_COMMIT();
    issue_loads(1, 1);
    CP_COMMIT();

    const int NK = Dm / 32;
    for (int kc = 0; kc < NK; kc++) {
        // drain correctly: on the last iteration the newest pending group IS
        // the buffer we read, so wait_group 0 there.
        if (kc == NK - 1) { CP_WAIT0(); } else { CP_WAIT1(); }
        __syncthreads();

        int buf = kc % G_STAGES;
        uint32_t bA = smb + (uint32_t)buf * GT_BUF * 2;
        uint32_t sA_u = bA;
        uint32_t sB_u = bA + GT_TILE * 2;

        #pragma unroll
        for (int k16 = 0; k16 < 2; k16++) {
            uint32_t bh[2][4];
            #pragma unroll
            for (int nb = 0; nb < 2; nb++)
                ldsm_x4(bh[nb], ldsm_addr_b(sB_u, wn + nb * 16, k16 * 16, GST, lane));
            #pragma unroll
            for (int mi = 0; mi < 4; mi++) {
                uint32_t ah[4];
                ldsm_x4(ah, ldsm_addr_rc(sA_u, wm + mi * 16, k16 * 16, GST, lane));
                #pragma unroll
                for (int nf = 0; nf < 4; nf++)
                    mma_f16(acc[mi][nf], ah, &bh[nf >> 1][(nf & 1) * 2]);
            }
        }

        if (kc + 2 < NK) {
            issue_loads(kc + 2, (kc + 2) % G_STAGES);
            CP_COMMIT();
        }
    }

    #pragma unroll
    for (int mi = 0; mi < 4; mi++) {
        int row = m0 + wm + mi * 16 + (lane >> 2);
        #pragma unroll
        for (int nf = 0; nf < 4; nf++) {
            int col = n0 + wn + nf * 8 + (lane & 3) * 2;
            float b0 = job.bias[col], b1 = job.bias[col + 1];
            #pragma unroll
            for (int half = 0; half < 2; half++) {
                int r = row + half * 8;
                float v0 = acc[mi][nf][half * 2 + 0] + b0;
                float v1 = acc[mi][nf][half * 2 + 1] + b1;
                size_t o = (size_t)r * Dm + col;
                if (OUT == 2) {
                    v0 *= job.scale;
                    v1 *= job.scale;
                    *(__half2*)(job.Cs + o) = __floats2half2_rn(v0, v1);
                } else {
                    float2 v; v.x = v0; v.y = v1;
                    *(float2*)(job.Cf + o) = v;
                }
            }
        }
    }
}

// ---------------------------------------------------------------------------
// Flash attention, single-pass fp16 HMMA. 4 warps x 32 q-rows (Br=128),
// Bc=64, Dk=64. Q frags register-resident; K/V 3-stage cp.async pipeline.
// p = 2^(q.k) (Q pre-scaled); output fp16.
// ---------------------------------------------------------------------------
#define FST 72
#define FQ_B   (128 * FST * 2)                 // 18432
#define FT_B   (64 * FST * 2)                  // 9216
#define FBUF_B (2 * FT_B)                      // K + V
#define F_STAGES 3
#define FLASH_SMEM_BYTES (FQ_B + F_STAGES * FBUF_B)   // 73728

__global__ __launch_bounds__(128, 2) void flash_f16(
    const __half* __restrict__ Qs, const __half* __restrict__ Ks,
    const __half* __restrict__ Vs, __half* __restrict__ As)
{
    extern __shared__ __align__(16) __half fsm[];
    const int tid = threadIdx.x;
    const int warp = tid >> 5, lane = tid & 31;
    const int qt = blockIdx.x, h = blockIdx.y, b = blockIdx.z;
    const int wq = warp * 32;
    const uint32_t smb = smem_u32(fsm);

    // ---- stage Q (128x64 fp16) ----
    #pragma unroll
    for (int t = 0; t < 8; t++) {
        int c = tid + t * 128;
        int r = c >> 3, ch = c & 7;
        size_t g = (size_t)(b * Ss + qt * 128 + r) * Dm + h * Dk + ch * 8;
        *(uint4*)(&fsm[r * FST + ch * 8]) = *(const uint4*)(Qs + g);
    }

    auto issue_kv = [&](int kt, int buf) {
        uint32_t base = smb + FQ_B + (uint32_t)buf * FBUF_B;
        const __half* srcs[2] = { Ks, Vs };
        #pragma unroll
        for (int t = 0; t < 8; t++) {
            int c = tid + t * 128;
            int tile = c >> 9, idx = c & 511;
            int r = idx >> 3, ch = idx & 7;
            size_t g = (size_t)(b * Ss + kt * 64 + r) * Dm + h * Dk + ch * 8;
            uint32_t s = base + (uint32_t)tile * FT_B + (uint32_t)(r * FST + ch * 8) * 2;
            cp_async16(s, srcs[tile] + g);
        }
    };

    issue_kv(0, 0);
    CP_COMMIT();
    issue_kv(1, 1);
    CP_COMMIT();
    __syncthreads();   // Q plane visible to all warps

    // ---- Q fragments resident in registers ----
    uint32_t qf[2][4][4];
    #pragma unroll
    for (int mi = 0; mi < 2; mi++)
        #pragma unroll
        for (int ki = 0; ki < 4; ki++)
            ldsm_x4(qf[mi][ki], ldsm_addr_rc(smb, wq + mi * 16, ki * 16, FST, lane));

    float oacc[2][8][4];
    #pragma unroll
    for (int mi = 0; mi < 2; mi++)
        #pragma unroll
        for (int nf = 0; nf < 8; nf++)
            #pragma unroll
            for (int j = 0; j < 4; j++) oacc[mi][nf][j] = 0.0f;
    float lsum[2][2] = {{0.0f, 0.0f}, {0.0f, 0.0f}};

    const int NT = Ss / 64;
    for (int kt = 0; kt < NT; kt++) {
        if (kt == NT - 1) { CP_WAIT0(); } else { CP_WAIT1(); }
        __syncthreads();

        int buf = kt % F_STAGES;
        uint32_t sKs = smb + FQ_B + (uint32_t)buf * FBUF_B;
        uint32_t sVs = sKs + FT_B;

        // ---- S = Q K^T ----
        float s[2][8][4];
        #pragma unroll
        for (int mi = 0; mi < 2; mi++)
            #pragma unroll
            for (int nf = 0; nf < 8; nf++)
                #pragma unroll
                for (int j = 0; j < 4; j++) s[mi][nf][j] = 0.0f;

        #pragma unroll
        for (int ki = 0; ki < 4; ki++) {
            #pragma unroll
            for (int nb = 0; nb < 4; nb++) {
                uint32_t kf[4];
                ldsm_x4(kf, ldsm_addr_b(sKs, nb * 16, ki * 16, FST, lane));
                #pragma unroll
                for (int half = 0; half < 2; half++) {
                    mma_f16(s[0][nb * 2 + half], qf[0][ki], &kf[half * 2]);
                    mma_f16(s[1][nb * 2 + half], qf[1][ki], &kf[half * 2]);
                }
            }
        }

        // ---- p = 2^s ; per-lane partial row sums ----
        #pragma unroll
        for (int mi = 0; mi < 2; mi++)
            #pragma unroll
            for (int nf = 0; nf < 8; nf++) {
                s[mi][nf][0] = ex2(s[mi][nf][0]);
                s[mi][nf][1] = ex2(s[mi][nf][1]);
                s[mi][nf][2] = ex2(s[mi][nf][2]);
                s[mi][nf][3] = ex2(s[mi][nf][3]);
                lsum[mi][0] += s[mi][nf][0] + s[mi][nf][1];
                lsum[mi][1] += s[mi][nf][2] + s[mi][nf][3];
            }

        // ---- P -> fp16 A-frags ----
        uint32_t aP[2][4][4];
        #pragma unroll
        for (int mi = 0; mi < 2; mi++)
            #pragma unroll
            for (int ki = 0; ki < 4; ki++)
                #pragma unroll
                for (int j = 0; j < 4; j++) {
                    int nf = 2 * ki + (j >> 1);
                    int e0 = (j & 1) * 2;
                    aP[mi][ki][j] = pack_h2(s[mi][nf][e0], s[mi][nf][e0 + 1]);
                }

        // ---- O += P V ----
        #pragma unroll
        for (int ki = 0; ki < 4; ki++) {
            #pragma unroll
            for (int nb = 0; nb < 4; nb++) {
                uint32_t vf[4];
                ldsm_x4_t(vf, ldsm_addr_rc(sVs, ki * 16, nb * 16, FST, lane));
                #pragma unroll
                for (int half = 0; half < 2; half++) {
                    mma_f16(oacc[0][nb * 2 + half], aP[0][ki], &vf[half * 2]);
                    mma_f16(oacc[1][nb * 2 + half], aP[1][ki], &vf[half * 2]);
                }
            }
        }

        if (kt + 2 < NT) {
            issue_kv(kt + 2, (kt + 2) % F_STAGES);
            CP_COMMIT();
        }
    }

    #pragma unroll
    for (int mi = 0; mi < 2; mi++)
        #pragma unroll
        for (int hf = 0; hf < 2; hf++) {
            #pragma unroll
            for (int off = 1; off < 4; off <<= 1)
                lsum[mi][hf] += __shfl_xor_sync(0xffffffffu, lsum[mi][hf], off);
        }

    #pragma unroll
    for (int mi = 0; mi < 2; mi++) {
        float inv0 = 1.0f / lsum[mi][0], inv1 = 1.0f / lsum[mi][1];
        int row = b * Ss + qt * 128 + wq + mi * 16 + (lane >> 2);
        #pragma unroll
        for (int nf = 0; nf < 8; nf++) {
            int col = h * Dk + nf * 8 + (lane & 3) * 2;
            #pragma unroll
            for (int half = 0; half < 2; half++) {
                float inv = half ? inv1 : inv0;
                float v0 = oacc[mi][nf][half * 2 + 0] * inv;
                float v1 = oacc[mi][nf][half * 2 + 1] * inv;
                size_t o = (size_t)(row + half * 8) * Dm + col;
                *(__half2*)(As + o) = __floats2half2_rn(v0, v1);
            }
        }
    }
}

// ---------------------------------------------------------------------------
extern "C" void kernel_launch(void* const* d_in, const int* in_sizes, int n_in,
                              void* d_out, int out_size)
{
    const float* x   = (const float*)d_in[0];
    const float* w_q = (const float*)d_in[1];
    const float* b_q = (const float*)d_in[2];
    const float* w_k = (const float*)d_in[3];
    const float* b_k = (const float*)d_in[4];
    const float* w_v = (const float*)d_in[5];
    const float* b_v = (const float*)d_in[6];
    const float* w_o = (const float*)d_in[7];
    const float* b_o = (const float*)d_in[8];
    float* out = (float*)d_out;

    __half *xs, *Qsp, *Ksp, *Vsp, *Asp, *wT;
    cudaGetSymbolAddress((void**)&xs, g_xs);
    cudaGetSymbolAddress((void**)&Qsp, g_Qs);
    cudaGetSymbolAddress((void**)&Ksp, g_Ks);
    cudaGetSymbolAddress((void**)&Vsp, g_Vs);
    cudaGetSymbolAddress((void**)&Asp, g_As);
    cudaGetSymbolAddress((void**)&wT, g_wT);
    const size_t WSZ = (size_t)Dm * Dm;

    cudaFuncSetAttribute(tc_gemm<0>,
                         cudaFuncAttributeMaxDynamicSharedMemorySize, GEMM_SMEM_BYTES);
    cudaFuncSetAttribute(tc_gemm<2>,
                         cudaFuncAttributeMaxDynamicSharedMemorySize, GEMM_SMEM_BYTES);
    cudaFuncSetAttribute(flash_f16,
                         cudaFuncAttributeMaxDynamicSharedMemorySize, FLASH_SMEM_BYTES);

    // fused prep: transpose+convert 4 weights (z<4) + convert x (z==4)
    {
        dim3 tg(32, 32, 5), tb(32, 8);
        prep_kernel<<<tg, tb>>>(x, w_q, w_k, w_v, w_o, xs, wT);
    }

    // fused QKV projection -> fp16 (Q pre-scaled by log2e/8)
    {
        GemmJobs3 jobs;
        jobs.j[0] = { wT + 0 * WSZ, b_q, nullptr, Qsp, QSCALE };
        jobs.j[1] = { wT + 1 * WSZ, b_k, nullptr, Ksp, 1.0f };
        jobs.j[2] = { wT + 2 * WSZ, b_v, nullptr, Vsp, 1.0f };
        dim3 g(Dm / 128, MR / 128, 3);
        tc_gemm<2><<<g, 256, GEMM_SMEM_BYTES>>>(xs, jobs);
    }

    // flash attention (fp16 single-pass, 3-stage KV pipeline)
    {
        dim3 agrid(Ss / 128, Hh, Bb);   // (16,16,2)
        flash_f16<<<agrid, 128, FLASH_SMEM_BYTES>>>(Qsp, Ksp, Vsp, Asp);
    }

    // output projection (fp16 single-pass, fp32 out + bias)
    {
        GemmJobs3 jobs;
        jobs.j[0] = { wT + 3 * WSZ, b_o, out, nullptr, 1.0f };
        jobs.j[1] = jobs.j[0];
        jobs.j[2] = jobs.j[0];
        dim3 g(Dm / 128, MR / 128, 1);
        tc_gemm<0><<<g, 256, GEMM_SMEM_BYTES>>>(Asp, jobs);
    }
}